// round 10
// baseline (speedup 1.0000x reference)
#include <cuda_runtime.h>
#include <cuda_bf16.h>
#include <cstdint>

// Problem shape (fixed by the dataset)
#define B 64
#define S 512
#define DD 512

#define NEG_ORD ((int)0xB19194D7)   // ordf(-1e9f)
#define NEGF (-1e9f)

// ---------------- global scratch (no allocations allowed) ----------------
__device__ __align__(16) __nv_bfloat16 g_A_hi[(size_t)B * S * DD];
__device__ __align__(16) __nv_bfloat16 g_A_lo[(size_t)B * S * DD];
__device__ __align__(16) __nv_bfloat16 g_B_hi[(size_t)B * S * DD];
__device__ __align__(16) __nv_bfloat16 g_B_lo[(size_t)B * S * DD];
__device__ int g_rowmax[B * S];
__device__ int g_colmax[B * S];

// ---------------- helpers ----------------
__device__ __forceinline__ int ordf(float f) {
    int i = __float_as_int(f);
    return (i >= 0) ? i : (i ^ 0x7FFFFFFF);
}
__device__ __forceinline__ float deord(int s) {
    return __int_as_float((s >= 0) ? s : (s ^ 0x7FFFFFFF));
}
__device__ __forceinline__ uint32_t smem_u32(const void* p) {
    uint32_t a;
    asm("{ .reg .u64 t; cvta.to.shared.u64 t, %1; cvt.u32.u64 %0, t; }" : "=r"(a) : "l"(p));
    return a;
}

#define CP_ASYNC16(dst, src) \
    asm volatile("cp.async.cg.shared.global [%0], [%1], 16;" :: "r"(dst), "l"(src) : "memory")
#define CP_COMMIT()  asm volatile("cp.async.commit_group;" ::: "memory")
#define CP_WAIT(n)   asm volatile("cp.async.wait_group %0;" :: "n"(n) : "memory")

#define LDSM_X4(r0, r1, r2, r3, addr) \
    asm volatile("ldmatrix.sync.aligned.m8n8.x4.shared.b16 {%0,%1,%2,%3}, [%4];" \
                 : "=r"(r0), "=r"(r1), "=r"(r2), "=r"(r3) : "r"(addr))

#define MMA_BF16(c, a, b0v, b1v) \
    asm volatile("mma.sync.aligned.m16n8k16.row.col.f32.bf16.bf16.f32 " \
                 "{%0,%1,%2,%3}, {%4,%5,%6,%7}, {%8,%9}, {%0,%1,%2,%3};" \
                 : "+f"((c)[0]), "+f"((c)[1]), "+f"((c)[2]), "+f"((c)[3]) \
                 : "r"((a)[0]), "r"((a)[1]), "r"((a)[2]), "r"((a)[3]), "r"(b0v), "r"(b1v))

// ---------------- prep: normalize + bf16 hi/lo split ----------------
template <int SIDE>
__global__ void k_prep(const float* __restrict__ in) {
    int row  = (blockIdx.x * blockDim.x + threadIdx.x) >> 5;
    int lane = threadIdx.x & 31;
    if (row >= B * S) return;
    const float4* rp = (const float4*)(in + (size_t)row * DD);

    float4 v0a = rp[2 * lane],        v0b = rp[2 * lane + 1];
    float4 v1a = rp[2 * (lane + 32)], v1b = rp[2 * (lane + 32) + 1];

    float ss = 0.f;
    ss = fmaf(v0a.x, v0a.x, ss); ss = fmaf(v0a.y, v0a.y, ss);
    ss = fmaf(v0a.z, v0a.z, ss); ss = fmaf(v0a.w, v0a.w, ss);
    ss = fmaf(v0b.x, v0b.x, ss); ss = fmaf(v0b.y, v0b.y, ss);
    ss = fmaf(v0b.z, v0b.z, ss); ss = fmaf(v0b.w, v0b.w, ss);
    ss = fmaf(v1a.x, v1a.x, ss); ss = fmaf(v1a.y, v1a.y, ss);
    ss = fmaf(v1a.z, v1a.z, ss); ss = fmaf(v1a.w, v1a.w, ss);
    ss = fmaf(v1b.x, v1b.x, ss); ss = fmaf(v1b.y, v1b.y, ss);
    ss = fmaf(v1b.z, v1b.z, ss); ss = fmaf(v1b.w, v1b.w, ss);
#pragma unroll
    for (int o = 16; o > 0; o >>= 1) ss += __shfl_xor_sync(0xFFFFFFFFu, ss, o);
    float inv = 1.0f / fmaxf(sqrtf(ss), 1e-8f);

    __nv_bfloat16* dhi = (SIDE == 0) ? g_A_hi : g_B_hi;
    __nv_bfloat16* dlo = (SIDE == 0) ? g_A_lo : g_B_lo;
    if (lane == 0) {
        if (SIDE == 0) g_rowmax[row] = NEG_ORD; else g_colmax[row] = NEG_ORD;
    }

#pragma unroll
    for (int half = 0; half < 2; half++) {
        float x[8];
        if (half == 0) {
            x[0] = v0a.x; x[1] = v0a.y; x[2] = v0a.z; x[3] = v0a.w;
            x[4] = v0b.x; x[5] = v0b.y; x[6] = v0b.z; x[7] = v0b.w;
        } else {
            x[0] = v1a.x; x[1] = v1a.y; x[2] = v1a.z; x[3] = v1a.w;
            x[4] = v1b.x; x[5] = v1b.y; x[6] = v1b.z; x[7] = v1b.w;
        }
        __nv_bfloat16 h[8], l[8];
#pragma unroll
        for (int u = 0; u < 8; u++) {
            float v = x[u] * inv;
            h[u] = __float2bfloat16(v);
            l[u] = __float2bfloat16(v - __bfloat162float(h[u]));
        }
        size_t idx = (size_t)row * DD + (size_t)(lane + 32 * half) * 8;
        *(uint4*)(dhi + idx) = *(uint4*)h;
        *(uint4*)(dlo + idx) = *(uint4*)l;
    }
}

// ---------------- GEMM: bf16 mma.sync split-precision + masked row/col max ----------------
// CTA 256 threads (8 warps), tile 128x128, k-chunk 32, 2-stage cp.async pipeline,
// 2 CTAs/SM. Warp grid 4(row) x 2(col): warp tile 32x64 = 2 m16 x 8 n8 frags.
// Smem rows are stride-80B padded (no XOR swizzle): 8 consecutive rows hit 8
// distinct 16B bank-groups (offsets mod 128 = {0,80,32,112,64,16,96,48}).
// Per k16: 3 passes of 16 independent MMAs (hh, lh, hl); aux regs shared
// between A_lo (pass 2) and B_lo (pass 3).
#define KCH 32
#define NCHUNK (DD / KCH)
#define TM 128
#define TN 128
#define ROWB 80                       // padded row stride in bytes (4x16B granules + 16B pad)
#define TILE_BYTES (128 * ROWB)       // 10240
#define OFF_AHI 0
#define OFF_ALO (TILE_BYTES)
#define OFF_BHI (2 * TILE_BYTES)
#define OFF_BLO (3 * TILE_BYTES)
#define STAGE_BYTES (4 * TILE_BYTES)  // 40960
#define DYN_SMEM (2 * STAGE_BYTES)    // 81920

__global__ __launch_bounds__(256, 2) void k_gemm(const int* __restrict__ mask1,
                                                 const int* __restrict__ mask2) {
    extern __shared__ __align__(1024) char smem[];
    __shared__ int m1s[TM], m2s[TN];

    const uint32_t sb = smem_u32(smem);
    const int tid  = threadIdx.x;
    const int wid  = tid >> 5;
    const int lane = tid & 31;
    const int b  = blockIdx.z;
    const int ib = blockIdx.y;
    const int jb = blockIdx.x;
    const int i0 = ib * TM;
    const int j0 = jb * TN;

    if (tid < TM) m1s[tid] = mask1[b * S + i0 + tid];
    else if (tid < TM + TN) m2s[tid - TM] = mask2[b * S + j0 + (tid - TM)];

    const __nv_bfloat16* pAhi = g_A_hi + ((size_t)b * S + i0) * DD;
    const __nv_bfloat16* pAlo = g_A_lo + ((size_t)b * S + i0) * DD;
    const __nv_bfloat16* pBhi = g_B_hi + ((size_t)b * S + j0) * DD;
    const __nv_bfloat16* pBlo = g_B_lo + ((size_t)b * S + j0) * DD;

    // loader: 512 granules per array per chunk (128 rows x 4 granules of 8 bf16).
    // G = tid + 256*u: row = G & 127, kg = G >> 7  -> conflict-free STS.128.
    auto issue_chunk = [&](int kc, int st) {
        uint32_t stg = sb + st * STAGE_BYTES;
        size_t kbase = (size_t)kc * KCH;
#pragma unroll
        for (int u = 0; u < 2; u++) {
            int G = tid + 256 * u;
            int row = G & 127, kg = G >> 7;
            size_t so = (size_t)row * DD + kbase + kg * 8;
            uint32_t dd = (uint32_t)(row * ROWB + kg * 16);
            CP_ASYNC16(stg + OFF_AHI + dd, pAhi + so);
            CP_ASYNC16(stg + OFF_ALO + dd, pAlo + so);
            CP_ASYNC16(stg + OFF_BHI + dd, pBhi + so);
            CP_ASYNC16(stg + OFF_BLO + dd, pBlo + so);
        }
    };

    float acc[2][8][4];
#pragma unroll
    for (int mi = 0; mi < 2; mi++)
#pragma unroll
        for (int nj = 0; nj < 8; nj++)
#pragma unroll
            for (int r = 0; r < 4; r++) acc[mi][nj][r] = 0.f;

    const int wr = (wid & 3) * 32;    // 4 row groups
    const int wc = (wid >> 2) * 64;   // 2 col groups

    // ldmatrix lane address components
    const int a_r = (lane & 7) + 8 * ((lane >> 3) & 1);
    const int a_k = lane >> 4;
    const int b_r = (lane & 7) + 8 * (lane >> 4);
    const int b_k = (lane >> 3) & 1;

    issue_chunk(0, 0);
    CP_COMMIT();

#pragma unroll 1
    for (int t = 0; t < NCHUNK; t++) {
        if (t < NCHUNK - 1) {
            issue_chunk(t + 1, (t + 1) & 1);
            CP_COMMIT();
            CP_WAIT(1);
        } else {
            CP_WAIT(0);
        }
        __syncthreads();

        uint32_t stg = sb + (t & 1) * STAGE_BYTES;
#pragma unroll
        for (int ks = 0; ks < 2; ks++) {
            uint32_t ah[2][4], bh[4][4], aux[4][4];

#pragma unroll
            for (int mi = 0; mi < 2; mi++) {
                int row = wr + 16 * mi + a_r;
                uint32_t ad = stg + (uint32_t)(row * ROWB + (ks * 2 + a_k) * 16);
                LDSM_X4(ah[mi][0], ah[mi][1], ah[mi][2], ah[mi][3], ad + OFF_AHI);
            }
#pragma unroll
            for (int nb = 0; nb < 4; nb++) {
                int row = wc + 16 * nb + b_r;
                uint32_t bd = stg + (uint32_t)(row * ROWB + (ks * 2 + b_k) * 16);
                LDSM_X4(bh[nb][0], bh[nb][1], bh[nb][2], bh[nb][3], bd + OFF_BHI);
            }

            // pass 1: hi * hi (16 independent MMAs)
#pragma unroll
            for (int mi = 0; mi < 2; mi++)
#pragma unroll
                for (int nb = 0; nb < 4; nb++) {
                    MMA_BF16(acc[mi][2 * nb],     ah[mi], bh[nb][0], bh[nb][1]);
                    MMA_BF16(acc[mi][2 * nb + 1], ah[mi], bh[nb][2], bh[nb][3]);
                }

            // A-lo into aux[0..1]
#pragma unroll
            for (int mi = 0; mi < 2; mi++) {
                int row = wr + 16 * mi + a_r;
                uint32_t ad = stg + (uint32_t)(row * ROWB + (ks * 2 + a_k) * 16);
                LDSM_X4(aux[mi][0], aux[mi][1], aux[mi][2], aux[mi][3], ad + OFF_ALO);
            }
            // pass 2: lo * hi
#pragma unroll
            for (int mi = 0; mi < 2; mi++)
#pragma unroll
                for (int nb = 0; nb < 4; nb++) {
                    MMA_BF16(acc[mi][2 * nb],     aux[mi], bh[nb][0], bh[nb][1]);
                    MMA_BF16(acc[mi][2 * nb + 1], aux[mi], bh[nb][2], bh[nb][3]);
                }

            // B-lo into aux[0..3]
#pragma unroll
            for (int nb = 0; nb < 4; nb++) {
                int row = wc + 16 * nb + b_r;
                uint32_t bd = stg + (uint32_t)(row * ROWB + (ks * 2 + b_k) * 16);
                LDSM_X4(aux[nb][0], aux[nb][1], aux[nb][2], aux[nb][3], bd + OFF_BLO);
            }
            // pass 3: hi * lo
#pragma unroll
            for (int mi = 0; mi < 2; mi++)
#pragma unroll
                for (int nb = 0; nb < 4; nb++) {
                    MMA_BF16(acc[mi][2 * nb],     ah[mi], aux[nb][0], aux[nb][1]);
                    MMA_BF16(acc[mi][2 * nb + 1], ah[mi], aux[nb][2], aux[nb][3]);
                }
        }
        __syncthreads();
    }

    // -------- epilogue: masked row/col maxes from D fragments --------
    const int g  = lane >> 2;
    const int tg = lane & 3;

    int cmask[8][2];
#pragma unroll
    for (int nj = 0; nj < 8; nj++) {
        cmask[nj][0] = m2s[wc + 8 * nj + 2 * tg];
        cmask[nj][1] = m2s[wc + 8 * nj + 2 * tg + 1];
    }
    int rmask[2][2];
#pragma unroll
    for (int mi = 0; mi < 2; mi++) {
        rmask[mi][0] = m1s[wr + 16 * mi + g];
        rmask[mi][1] = m1s[wr + 16 * mi + g + 8];
    }

    // row maxes: reduce over tg lanes
#pragma unroll
    for (int mi = 0; mi < 2; mi++)
#pragma unroll
        for (int p = 0; p < 2; p++) {
            float rm = NEGF;
#pragma unroll
            for (int nj = 0; nj < 8; nj++) {
                if (cmask[nj][0]) rm = fmaxf(rm, acc[mi][nj][2 * p]);
                if (cmask[nj][1]) rm = fmaxf(rm, acc[mi][nj][2 * p + 1]);
            }
            rm = fmaxf(rm, __shfl_xor_sync(0xFFFFFFFFu, rm, 1));
            rm = fmaxf(rm, __shfl_xor_sync(0xFFFFFFFFu, rm, 2));
            if (tg == 0)
                atomicMax(&g_rowmax[b * S + i0 + wr + 16 * mi + g + 8 * p], ordf(rm));
        }

    // col maxes: reduce over g lanes
#pragma unroll
    for (int nj = 0; nj < 8; nj++)
#pragma unroll
        for (int q = 0; q < 2; q++) {
            float cm = NEGF;
#pragma unroll
            for (int mi = 0; mi < 2; mi++) {
                if (rmask[mi][0]) cm = fmaxf(cm, acc[mi][nj][q]);
                if (rmask[mi][1]) cm = fmaxf(cm, acc[mi][nj][2 + q]);
            }
            cm = fmaxf(cm, __shfl_xor_sync(0xFFFFFFFFu, cm, 4));
            cm = fmaxf(cm, __shfl_xor_sync(0xFFFFFFFFu, cm, 8));
            cm = fmaxf(cm, __shfl_xor_sync(0xFFFFFFFFu, cm, 16));
            if (g == 0)
                atomicMax(&g_colmax[b * S + j0 + wc + 8 * nj + 2 * tg + q], ordf(cm));
        }
}

// ---------------- final masked sums ----------------
__global__ void k_final(const int* __restrict__ mask1, const int* __restrict__ mask2,
                        float* __restrict__ out) {
    __shared__ float ssum[256];
    __shared__ int   scnt[256];
    const int b = blockIdx.x;
    const int tid = threadIdx.x;

    float s = 0.f;
    int   n = 0;
    for (int i = tid; i < S; i += 256) {
        int m1 = mask1[b * S + i];
        if (m1) s += deord(g_rowmax[b * S + i]);
        n += m1;
        int m2 = mask2[b * S + i];
        if (m2) s += deord(g_colmax[b * S + i]);
        n += m2;
    }
    ssum[tid] = s; scnt[tid] = n;
    __syncthreads();
    for (int o = 128; o > 0; o >>= 1) {
        if (tid < o) { ssum[tid] += ssum[tid + o]; scnt[tid] += scnt[tid + o]; }
        __syncthreads();
    }
    if (tid == 0) out[b] = ssum[0] / (float)scnt[0];
}

// ---------------- launch ----------------
extern "C" void kernel_launch(void* const* d_in, const int* in_sizes, int n_in,
                              void* d_out, int out_size) {
    const float* emb1  = (const float*)d_in[0];
    const float* emb2  = (const float*)d_in[1];
    const int*   mask1 = (const int*)d_in[2];
    const int*   mask2 = (const int*)d_in[3];
    float*       out   = (float*)d_out;

    static bool attr_set = false;
    if (!attr_set) {
        cudaFuncSetAttribute(k_gemm, cudaFuncAttributeMaxDynamicSharedMemorySize, DYN_SMEM);
        attr_set = true;
    }

    // 1) prep (one warp per row)
    k_prep<0><<<(B * S) / 8, 256>>>(emb1);
    k_prep<1><<<(B * S) / 8, 256>>>(emb2);

    // 2) GEMM + masked maxes: grid (jb=4, ib=4, b=64) = 1024 CTAs, 2 CTAs/SM
    dim3 grid(S / TN, S / TM, B);
    k_gemm<<<grid, 256, DYN_SMEM>>>(mask1, mask2);

    // 3) final
    k_final<<<B, 256>>>(mask1, mask2, out);
}

// round 12
// speedup vs baseline: 2.0858x; 2.0858x over previous
#include <cuda_runtime.h>
#include <cuda_bf16.h>
#include <cstdint>

// Problem shape (fixed by the dataset)
#define B 64
#define S 512
#define DD 512

#define NEG_ORD ((int)0xB19194D7)   // ordf(-1e9f)
#define NEGF (-1e9f)

// ---------------- global scratch (no allocations allowed) ----------------
__device__ __align__(16) __nv_bfloat16 g_A_hi[(size_t)B * S * DD];
__device__ __align__(16) __nv_bfloat16 g_A_lo[(size_t)B * S * DD];
__device__ __align__(16) __nv_bfloat16 g_B_hi[(size_t)B * S * DD];
__device__ __align__(16) __nv_bfloat16 g_B_lo[(size_t)B * S * DD];
__device__ int g_rowmax[B * S];
__device__ int g_colmax[B * S];

// ---------------- helpers ----------------
__device__ __forceinline__ int ordf(float f) {
    int i = __float_as_int(f);
    return (i >= 0) ? i : (i ^ 0x7FFFFFFF);
}
__device__ __forceinline__ float deord(int s) {
    return __int_as_float((s >= 0) ? s : (s ^ 0x7FFFFFFF));
}
__device__ __forceinline__ uint32_t smem_u32(const void* p) {
    uint32_t a;
    asm("{ .reg .u64 t; cvta.to.shared.u64 t, %1; cvt.u32.u64 %0, t; }" : "=r"(a) : "l"(p));
    return a;
}

#define CP_ASYNC16(dst, src) \
    asm volatile("cp.async.cg.shared.global [%0], [%1], 16;" :: "r"(dst), "l"(src) : "memory")
#define CP_COMMIT()  asm volatile("cp.async.commit_group;" ::: "memory")
#define CP_WAIT(n)   asm volatile("cp.async.wait_group %0;" :: "n"(n) : "memory")

#define LDSM_X4(r0, r1, r2, r3, addr) \
    asm volatile("ldmatrix.sync.aligned.m8n8.x4.shared.b16 {%0,%1,%2,%3}, [%4];" \
                 : "=r"(r0), "=r"(r1), "=r"(r2), "=r"(r3) : "r"(addr))

#define MMA_BF16(c, a, b0v, b1v) \
    asm volatile("mma.sync.aligned.m16n8k16.row.col.f32.bf16.bf16.f32 " \
                 "{%0,%1,%2,%3}, {%4,%5,%6,%7}, {%8,%9}, {%0,%1,%2,%3};" \
                 : "+f"((c)[0]), "+f"((c)[1]), "+f"((c)[2]), "+f"((c)[3]) \
                 : "r"((a)[0]), "r"((a)[1]), "r"((a)[2]), "r"((a)[3]), "r"(b0v), "r"(b1v))

// ---------------- prep: normalize + bf16 hi/lo split (mask-skipped) ----------------
// One warp per row. Rows beyond the valid prefix are skipped entirely: their
// stale/zero scratch contents only ever feed mask-discarded outputs.
template <int SIDE>
__global__ void k_prep(const float* __restrict__ in, const int* __restrict__ mask) {
    int row  = (blockIdx.x * blockDim.x + threadIdx.x) >> 5;
    int lane = threadIdx.x & 31;
    if (row >= B * S) return;

    if (lane == 0) {
        if (SIDE == 0) g_rowmax[row] = NEG_ORD; else g_colmax[row] = NEG_ORD;
    }
    if (mask[row] == 0) return;   // invalid row: never contributes

    const float4* rp = (const float4*)(in + (size_t)row * DD);

    float4 v0a = rp[2 * lane],        v0b = rp[2 * lane + 1];
    float4 v1a = rp[2 * (lane + 32)], v1b = rp[2 * (lane + 32) + 1];

    float ss = 0.f;
    ss = fmaf(v0a.x, v0a.x, ss); ss = fmaf(v0a.y, v0a.y, ss);
    ss = fmaf(v0a.z, v0a.z, ss); ss = fmaf(v0a.w, v0a.w, ss);
    ss = fmaf(v0b.x, v0b.x, ss); ss = fmaf(v0b.y, v0b.y, ss);
    ss = fmaf(v0b.z, v0b.z, ss); ss = fmaf(v0b.w, v0b.w, ss);
    ss = fmaf(v1a.x, v1a.x, ss); ss = fmaf(v1a.y, v1a.y, ss);
    ss = fmaf(v1a.z, v1a.z, ss); ss = fmaf(v1a.w, v1a.w, ss);
    ss = fmaf(v1b.x, v1b.x, ss); ss = fmaf(v1b.y, v1b.y, ss);
    ss = fmaf(v1b.z, v1b.z, ss); ss = fmaf(v1b.w, v1b.w, ss);
#pragma unroll
    for (int o = 16; o > 0; o >>= 1) ss += __shfl_xor_sync(0xFFFFFFFFu, ss, o);
    float inv = 1.0f / fmaxf(sqrtf(ss), 1e-8f);

    __nv_bfloat16* dhi = (SIDE == 0) ? g_A_hi : g_B_hi;
    __nv_bfloat16* dlo = (SIDE == 0) ? g_A_lo : g_B_lo;

#pragma unroll
    for (int half = 0; half < 2; half++) {
        float x[8];
        if (half == 0) {
            x[0] = v0a.x; x[1] = v0a.y; x[2] = v0a.z; x[3] = v0a.w;
            x[4] = v0b.x; x[5] = v0b.y; x[6] = v0b.z; x[7] = v0b.w;
        } else {
            x[0] = v1a.x; x[1] = v1a.y; x[2] = v1a.z; x[3] = v1a.w;
            x[4] = v1b.x; x[5] = v1b.y; x[6] = v1b.z; x[7] = v1b.w;
        }
        __nv_bfloat16 h[8], l[8];
#pragma unroll
        for (int u = 0; u < 8; u++) {
            float v = x[u] * inv;
            h[u] = __float2bfloat16(v);
            l[u] = __float2bfloat16(v - __bfloat162float(h[u]));
        }
        size_t idx = (size_t)row * DD + (size_t)(lane + 32 * half) * 8;
        *(uint4*)(dhi + idx) = *(uint4*)h;
        *(uint4*)(dlo + idx) = *(uint4*)l;
    }
}

// ---------------- GEMM: bf16 mma.sync split-precision + masked row/col max ----------------
// (R4 config: CTA 256 threads / 8 warps, tile 128x128, k-chunk 64, 2-stage
//  cp.async pipeline, XOR swizzle, warp grid 4(row)x2(col), warp tile 32x64.)
// NEW: prefix-mask tile skipping — tile needed iff it has >=1 valid row AND
//      >=1 valid column; masks are contiguous prefixes so element 0 decides.
#define KCH 64
#define NCHUNK (DD / KCH)
#define STAGE_BYTES 65536
#define OFF_AHI 0
#define OFF_ALO 16384
#define OFF_BHI 32768
#define OFF_BLO 49152

__global__ __launch_bounds__(256, 1) void k_gemm(const int* __restrict__ mask1,
                                                 const int* __restrict__ mask2) {
    extern __shared__ __align__(1024) char smem[];
    __shared__ int m1s[128], m2s[128];

    const uint32_t sb = smem_u32(smem);
    const int tid  = threadIdx.x;
    const int wid  = tid >> 5;
    const int lane = tid & 31;
    const int b  = blockIdx.z;
    const int ib = blockIdx.y;
    const int jb = blockIdx.x;
    const int i0 = ib * 128;
    const int j0 = jb * 128;

    // prefix-mask tile skip: uniform across CTA, no sync executed before this
    if (mask1[b * S + i0] == 0 || mask2[b * S + j0] == 0) return;

    if (tid < 128) m1s[tid] = mask1[b * S + i0 + tid];
    else           m2s[tid - 128] = mask2[b * S + j0 + (tid - 128)];

    const __nv_bfloat16* pAhi = g_A_hi + ((size_t)b * S + i0) * DD;
    const __nv_bfloat16* pAlo = g_A_lo + ((size_t)b * S + i0) * DD;
    const __nv_bfloat16* pBhi = g_B_hi + ((size_t)b * S + j0) * DD;
    const __nv_bfloat16* pBlo = g_B_lo + ((size_t)b * S + j0) * DD;

    // loader mapping: granule G = tid + 256*u (u<4): row = G>>3, kg = G&7
    int lrow[4], lkg[4];
    uint32_t ldst[4];
#pragma unroll
    for (int u = 0; u < 4; u++) {
        int G = tid + 256 * u;
        lrow[u] = G >> 3;
        lkg[u]  = G & 7;
        ldst[u] = (uint32_t)(lrow[u] * 128 + ((lkg[u] ^ (lrow[u] & 7)) * 16));
    }

    auto issue_chunk = [&](int kc, int st) {
        uint32_t stg = sb + st * STAGE_BYTES;
        size_t kbase = (size_t)kc * KCH;
#pragma unroll
        for (int u = 0; u < 4; u++) {
            size_t so = (size_t)lrow[u] * DD + kbase + lkg[u] * 8;
            CP_ASYNC16(stg + OFF_AHI + ldst[u], pAhi + so);
            CP_ASYNC16(stg + OFF_ALO + ldst[u], pAlo + so);
            CP_ASYNC16(stg + OFF_BHI + ldst[u], pBhi + so);
            CP_ASYNC16(stg + OFF_BLO + ldst[u], pBlo + so);
        }
    };

    float acc[2][8][4];
#pragma unroll
    for (int mi = 0; mi < 2; mi++)
#pragma unroll
        for (int nj = 0; nj < 8; nj++)
#pragma unroll
            for (int r = 0; r < 4; r++) acc[mi][nj][r] = 0.f;

    const int wr = (wid & 3) * 32;
    const int wc = (wid >> 2) * 64;

    // ldmatrix lane address components
    const int a_r = (lane & 7) + 8 * ((lane >> 3) & 1);
    const int a_k = lane >> 4;
    const int b_r = (lane & 7) + 8 * (lane >> 4);
    const int b_k = (lane >> 3) & 1;

    issue_chunk(0, 0);
    CP_COMMIT();

#pragma unroll 1
    for (int t = 0; t < NCHUNK; t++) {
        if (t < NCHUNK - 1) {
            issue_chunk(t + 1, (t + 1) & 1);
            CP_COMMIT();
            CP_WAIT(1);
        } else {
            CP_WAIT(0);
        }
        __syncthreads();

        uint32_t stg = sb + (t & 1) * STAGE_BYTES;
#pragma unroll
        for (int ks = 0; ks < 4; ks++) {
            const int kg0 = ks * 2;
            uint32_t ah[2][4], al[2][4], bh[4][4], bl[4][4];
#pragma unroll
            for (int mi = 0; mi < 2; mi++) {
                int row = wr + 16 * mi + a_r;
                uint32_t ad = stg + (uint32_t)(row * 128 + (((kg0 + a_k) ^ (row & 7)) * 16));
                LDSM_X4(ah[mi][0], ah[mi][1], ah[mi][2], ah[mi][3], ad + OFF_AHI);
                LDSM_X4(al[mi][0], al[mi][1], al[mi][2], al[mi][3], ad + OFF_ALO);
            }
#pragma unroll
            for (int nb = 0; nb < 4; nb++) {
                int row = wc + 16 * nb + b_r;
                uint32_t bd = stg + (uint32_t)(row * 128 + (((kg0 + b_k) ^ (row & 7)) * 16));
                LDSM_X4(bh[nb][0], bh[nb][1], bh[nb][2], bh[nb][3], bd + OFF_BHI);
                LDSM_X4(bl[nb][0], bl[nb][1], bl[nb][2], bl[nb][3], bd + OFF_BLO);
            }
#pragma unroll
            for (int mi = 0; mi < 2; mi++)
#pragma unroll
                for (int nb = 0; nb < 4; nb++) {
                    MMA_BF16(acc[mi][2 * nb],     ah[mi], bh[nb][0], bh[nb][1]);
                    MMA_BF16(acc[mi][2 * nb + 1], ah[mi], bh[nb][2], bh[nb][3]);
                    MMA_BF16(acc[mi][2 * nb],     al[mi], bh[nb][0], bh[nb][1]);
                    MMA_BF16(acc[mi][2 * nb + 1], al[mi], bh[nb][2], bh[nb][3]);
                    MMA_BF16(acc[mi][2 * nb],     ah[mi], bl[nb][0], bl[nb][1]);
                    MMA_BF16(acc[mi][2 * nb + 1], ah[mi], bl[nb][2], bl[nb][3]);
                }
        }
        __syncthreads();
    }

    // -------- epilogue: masked row/col maxes from D fragments --------
    const int g  = lane >> 2;
    const int tg = lane & 3;

    int cmask[8][2];
#pragma unroll
    for (int nj = 0; nj < 8; nj++) {
        cmask[nj][0] = m2s[wc + 8 * nj + 2 * tg];
        cmask[nj][1] = m2s[wc + 8 * nj + 2 * tg + 1];
    }
    int rmask[2][2];
#pragma unroll
    for (int mi = 0; mi < 2; mi++) {
        rmask[mi][0] = m1s[wr + 16 * mi + g];
        rmask[mi][1] = m1s[wr + 16 * mi + g + 8];
    }

    // row maxes
#pragma unroll
    for (int mi = 0; mi < 2; mi++)
#pragma unroll
        for (int p = 0; p < 2; p++) {
            float rm = NEGF;
#pragma unroll
            for (int nj = 0; nj < 8; nj++) {
                if (cmask[nj][0]) rm = fmaxf(rm, acc[mi][nj][2 * p]);
                if (cmask[nj][1]) rm = fmaxf(rm, acc[mi][nj][2 * p + 1]);
            }
            rm = fmaxf(rm, __shfl_xor_sync(0xFFFFFFFFu, rm, 1));
            rm = fmaxf(rm, __shfl_xor_sync(0xFFFFFFFFu, rm, 2));
            if (tg == 0)
                atomicMax(&g_rowmax[b * S + i0 + wr + 16 * mi + g + 8 * p], ordf(rm));
        }

    // col maxes
#pragma unroll
    for (int nj = 0; nj < 8; nj++)
#pragma unroll
        for (int q = 0; q < 2; q++) {
            float cm = NEGF;
#pragma unroll
            for (int mi = 0; mi < 2; mi++) {
                if (rmask[mi][0]) cm = fmaxf(cm, acc[mi][nj][q]);
                if (rmask[mi][1]) cm = fmaxf(cm, acc[mi][nj][2 + q]);
            }
            cm = fmaxf(cm, __shfl_xor_sync(0xFFFFFFFFu, cm, 4));
            cm = fmaxf(cm, __shfl_xor_sync(0xFFFFFFFFu, cm, 8));
            cm = fmaxf(cm, __shfl_xor_sync(0xFFFFFFFFu, cm, 16));
            if (g == 0)
                atomicMax(&g_colmax[b * S + j0 + wc + 8 * nj + 2 * tg + q], ordf(cm));
        }
}

// ---------------- final masked sums ----------------
__global__ void k_final(const int* __restrict__ mask1, const int* __restrict__ mask2,
                        float* __restrict__ out) {
    __shared__ float ssum[256];
    __shared__ int   scnt[256];
    const int b = blockIdx.x;
    const int tid = threadIdx.x;

    float s = 0.f;
    int   n = 0;
    for (int i = tid; i < S; i += 256) {
        int m1 = mask1[b * S + i];
        if (m1) s += deord(g_rowmax[b * S + i]);
        n += m1;
        int m2 = mask2[b * S + i];
        if (m2) s += deord(g_colmax[b * S + i]);
        n += m2;
    }
    ssum[tid] = s; scnt[tid] = n;
    __syncthreads();
    for (int o = 128; o > 0; o >>= 1) {
        if (tid < o) { ssum[tid] += ssum[tid + o]; scnt[tid] += scnt[tid + o]; }
        __syncthreads();
    }
    if (tid == 0) out[b] = ssum[0] / (float)scnt[0];
}

// ---------------- launch ----------------
extern "C" void kernel_launch(void* const* d_in, const int* in_sizes, int n_in,
                              void* d_out, int out_size) {
    const float* emb1  = (const float*)d_in[0];
    const float* emb2  = (const float*)d_in[1];
    const int*   mask1 = (const int*)d_in[2];
    const int*   mask2 = (const int*)d_in[3];
    float*       out   = (float*)d_out;

    static bool attr_set = false;
    if (!attr_set) {
        cudaFuncSetAttribute(k_gemm, cudaFuncAttributeMaxDynamicSharedMemorySize, 2 * STAGE_BYTES);
        attr_set = true;
    }

    // 1) prep (one warp per row, mask-skipped)
    k_prep<0><<<(B * S) / 8, 256>>>(emb1, mask1);
    k_prep<1><<<(B * S) / 8, 256>>>(emb2, mask2);

    // 2) GEMM + masked maxes: grid (jb=4, ib=4, b=64) = 1024 CTAs (many exit early)
    dim3 grid(S / 128, S / 128, B);
    k_gemm<<<grid, 256, 2 * STAGE_BYTES>>>(mask1, mask2);

    // 3) final
    k_final<<<B, 256>>>(mask1, mask2, out);
}

// round 14
// speedup vs baseline: 3.3244x; 1.5938x over previous
#include <cuda_runtime.h>
#include <cuda_fp16.h>
#include <cstdint>

// Problem shape (fixed by the dataset)
#define B 64
#define S 512
#define DD 512

#define NEG_ORD ((int)0xB19194D7)   // ordf(-1e9f)
#define NEGF (-1e9f)

// ---------------- global scratch (no allocations allowed) ----------------
__device__ __align__(16) __half g_A[(size_t)B * S * DD];   // normalized e1, fp16
__device__ __align__(16) __half g_B[(size_t)B * S * DD];   // normalized e2, fp16
__device__ int g_rowmax[B * S];
__device__ int g_colmax[B * S];

// ---------------- helpers ----------------
__device__ __forceinline__ int ordf(float f) {
    int i = __float_as_int(f);
    return (i >= 0) ? i : (i ^ 0x7FFFFFFF);
}
__device__ __forceinline__ float deord(int s) {
    return __int_as_float((s >= 0) ? s : (s ^ 0x7FFFFFFF));
}
__device__ __forceinline__ uint32_t smem_u32(const void* p) {
    uint32_t a;
    asm("{ .reg .u64 t; cvta.to.shared.u64 t, %1; cvt.u32.u64 %0, t; }" : "=r"(a) : "l"(p));
    return a;
}

#define CP_ASYNC16(dst, src) \
    asm volatile("cp.async.cg.shared.global [%0], [%1], 16;" :: "r"(dst), "l"(src) : "memory")
#define CP_COMMIT()  asm volatile("cp.async.commit_group;" ::: "memory")
#define CP_WAIT(n)   asm volatile("cp.async.wait_group %0;" :: "n"(n) : "memory")

#define LDSM_X4(r0, r1, r2, r3, addr) \
    asm volatile("ldmatrix.sync.aligned.m8n8.x4.shared.b16 {%0,%1,%2,%3}, [%4];" \
                 : "=r"(r0), "=r"(r1), "=r"(r2), "=r"(r3) : "r"(addr))

#define MMA_F16(c, a, b0v, b1v) \
    asm volatile("mma.sync.aligned.m16n8k16.row.col.f32.f16.f16.f32 " \
                 "{%0,%1,%2,%3}, {%4,%5,%6,%7}, {%8,%9}, {%0,%1,%2,%3};" \
                 : "+f"((c)[0]), "+f"((c)[1]), "+f"((c)[2]), "+f"((c)[3]) \
                 : "r"((a)[0]), "r"((a)[1]), "r"((a)[2]), "r"((a)[3]), "r"(b0v), "r"(b1v))

// ---------------- prep: normalize -> fp16 (mask-skipped) ----------------
// One warp per row. Rows beyond the valid prefix are skipped entirely: their
// stale/zero scratch contents only ever feed mask-discarded outputs.
template <int SIDE>
__global__ void k_prep(const float* __restrict__ in, const int* __restrict__ mask) {
    int row  = (blockIdx.x * blockDim.x + threadIdx.x) >> 5;
    int lane = threadIdx.x & 31;
    if (row >= B * S) return;

    if (lane == 0) {
        if (SIDE == 0) g_rowmax[row] = NEG_ORD; else g_colmax[row] = NEG_ORD;
    }
    if (mask[row] == 0) return;   // invalid row: never contributes

    const float4* rp = (const float4*)(in + (size_t)row * DD);

    float4 v0a = rp[2 * lane],        v0b = rp[2 * lane + 1];
    float4 v1a = rp[2 * (lane + 32)], v1b = rp[2 * (lane + 32) + 1];

    float ss = 0.f;
    ss = fmaf(v0a.x, v0a.x, ss); ss = fmaf(v0a.y, v0a.y, ss);
    ss = fmaf(v0a.z, v0a.z, ss); ss = fmaf(v0a.w, v0a.w, ss);
    ss = fmaf(v0b.x, v0b.x, ss); ss = fmaf(v0b.y, v0b.y, ss);
    ss = fmaf(v0b.z, v0b.z, ss); ss = fmaf(v0b.w, v0b.w, ss);
    ss = fmaf(v1a.x, v1a.x, ss); ss = fmaf(v1a.y, v1a.y, ss);
    ss = fmaf(v1a.z, v1a.z, ss); ss = fmaf(v1a.w, v1a.w, ss);
    ss = fmaf(v1b.x, v1b.x, ss); ss = fmaf(v1b.y, v1b.y, ss);
    ss = fmaf(v1b.z, v1b.z, ss); ss = fmaf(v1b.w, v1b.w, ss);
#pragma unroll
    for (int o = 16; o > 0; o >>= 1) ss += __shfl_xor_sync(0xFFFFFFFFu, ss, o);
    float inv = 1.0f / fmaxf(sqrtf(ss), 1e-8f);

    __half* dst = (SIDE == 0) ? g_A : g_B;

#pragma unroll
    for (int half_ = 0; half_ < 2; half_++) {
        float x[8];
        if (half_ == 0) {
            x[0] = v0a.x; x[1] = v0a.y; x[2] = v0a.z; x[3] = v0a.w;
            x[4] = v0b.x; x[5] = v0b.y; x[6] = v0b.z; x[7] = v0b.w;
        } else {
            x[0] = v1a.x; x[1] = v1a.y; x[2] = v1a.z; x[3] = v1a.w;
            x[4] = v1b.x; x[5] = v1b.y; x[6] = v1b.z; x[7] = v1b.w;
        }
        __half h[8];
#pragma unroll
        for (int u = 0; u < 8; u++) h[u] = __float2half(x[u] * inv);
        size_t idx = (size_t)row * DD + (size_t)(lane + 32 * half_) * 8;
        *(uint4*)(dst + idx) = *(uint4*)h;
    }
}

// ---------------- GEMM: fp16 mma.sync + masked row/col max ----------------
// CTA 256 threads / 8 warps, tile 128x128, k-chunk 64, 2-stage cp.async
// pipeline, XOR swizzle, warp grid 4(row)x2(col), warp tile 32x64.
// Prefix-mask tile skipping: tile needed iff element 0 of its row range AND
// of its column range are valid (masks are contiguous prefixes).
#define KCH 64
#define NCHUNK (DD / KCH)
#define STAGE_BYTES 32768
#define OFF_A 0
#define OFF_B 16384

__global__ __launch_bounds__(256, 1) void k_gemm(const int* __restrict__ mask1,
                                                 const int* __restrict__ mask2) {
    extern __shared__ __align__(1024) char smem[];
    __shared__ int m1s[128], m2s[128];

    const uint32_t sb = smem_u32(smem);
    const int tid  = threadIdx.x;
    const int wid  = tid >> 5;
    const int lane = tid & 31;
    const int b  = blockIdx.z;
    const int ib = blockIdx.y;
    const int jb = blockIdx.x;
    const int i0 = ib * 128;
    const int j0 = jb * 128;

    // prefix-mask tile skip: uniform across CTA, no sync executed before this
    if (mask1[b * S + i0] == 0 || mask2[b * S + j0] == 0) return;

    if (tid < 128) m1s[tid] = mask1[b * S + i0 + tid];
    else           m2s[tid - 128] = mask2[b * S + j0 + (tid - 128)];

    const __half* pA = g_A + ((size_t)b * S + i0) * DD;
    const __half* pB = g_B + ((size_t)b * S + j0) * DD;

    // loader mapping: granule G = tid + 256*u (u<4): row = G>>3, kg = G&7
    int lrow[4], lkg[4];
    uint32_t ldst[4];
#pragma unroll
    for (int u = 0; u < 4; u++) {
        int G = tid + 256 * u;
        lrow[u] = G >> 3;
        lkg[u]  = G & 7;
        ldst[u] = (uint32_t)(lrow[u] * 128 + ((lkg[u] ^ (lrow[u] & 7)) * 16));
    }

    auto issue_chunk = [&](int kc, int st) {
        uint32_t stg = sb + st * STAGE_BYTES;
        size_t kbase = (size_t)kc * KCH;
#pragma unroll
        for (int u = 0; u < 4; u++) {
            size_t so = (size_t)lrow[u] * DD + kbase + lkg[u] * 8;
            CP_ASYNC16(stg + OFF_A + ldst[u], pA + so);
            CP_ASYNC16(stg + OFF_B + ldst[u], pB + so);
        }
    };

    float acc[2][8][4];
#pragma unroll
    for (int mi = 0; mi < 2; mi++)
#pragma unroll
        for (int nj = 0; nj < 8; nj++)
#pragma unroll
            for (int r = 0; r < 4; r++) acc[mi][nj][r] = 0.f;

    const int wr = (wid & 3) * 32;
    const int wc = (wid >> 2) * 64;

    // ldmatrix lane address components
    const int a_r = (lane & 7) + 8 * ((lane >> 3) & 1);
    const int a_k = lane >> 4;
    const int b_r = (lane & 7) + 8 * (lane >> 4);
    const int b_k = (lane >> 3) & 1;

    issue_chunk(0, 0);
    CP_COMMIT();

#pragma unroll 1
    for (int t = 0; t < NCHUNK; t++) {
        if (t < NCHUNK - 1) {
            issue_chunk(t + 1, (t + 1) & 1);
            CP_COMMIT();
            CP_WAIT(1);
        } else {
            CP_WAIT(0);
        }
        __syncthreads();

        uint32_t stg = sb + (t & 1) * STAGE_BYTES;
#pragma unroll
        for (int ks = 0; ks < 4; ks++) {
            const int kg0 = ks * 2;
            uint32_t ah[2][4], bh[4][4];
#pragma unroll
            for (int mi = 0; mi < 2; mi++) {
                int row = wr + 16 * mi + a_r;
                uint32_t ad = stg + (uint32_t)(row * 128 + (((kg0 + a_k) ^ (row & 7)) * 16));
                LDSM_X4(ah[mi][0], ah[mi][1], ah[mi][2], ah[mi][3], ad + OFF_A);
            }
#pragma unroll
            for (int nb = 0; nb < 4; nb++) {
                int row = wc + 16 * nb + b_r;
                uint32_t bd = stg + (uint32_t)(row * 128 + (((kg0 + b_k) ^ (row & 7)) * 16));
                LDSM_X4(bh[nb][0], bh[nb][1], bh[nb][2], bh[nb][3], bd + OFF_B);
            }
#pragma unroll
            for (int mi = 0; mi < 2; mi++)
#pragma unroll
                for (int nb = 0; nb < 4; nb++) {
                    MMA_F16(acc[mi][2 * nb],     ah[mi], bh[nb][0], bh[nb][1]);
                    MMA_F16(acc[mi][2 * nb + 1], ah[mi], bh[nb][2], bh[nb][3]);
                }
        }
        __syncthreads();
    }

    // -------- epilogue: masked row/col maxes from D fragments --------
    const int g  = lane >> 2;
    const int tg = lane & 3;

    int cmask[8][2];
#pragma unroll
    for (int nj = 0; nj < 8; nj++) {
        cmask[nj][0] = m2s[wc + 8 * nj + 2 * tg];
        cmask[nj][1] = m2s[wc + 8 * nj + 2 * tg + 1];
    }
    int rmask[2][2];
#pragma unroll
    for (int mi = 0; mi < 2; mi++) {
        rmask[mi][0] = m1s[wr + 16 * mi + g];
        rmask[mi][1] = m1s[wr + 16 * mi + g + 8];
    }

    // row maxes
#pragma unroll
    for (int mi = 0; mi < 2; mi++)
#pragma unroll
        for (int p = 0; p < 2; p++) {
            float rm = NEGF;
#pragma unroll
            for (int nj = 0; nj < 8; nj++) {
                if (cmask[nj][0]) rm = fmaxf(rm, acc[mi][nj][2 * p]);
                if (cmask[nj][1]) rm = fmaxf(rm, acc[mi][nj][2 * p + 1]);
            }
            rm = fmaxf(rm, __shfl_xor_sync(0xFFFFFFFFu, rm, 1));
            rm = fmaxf(rm, __shfl_xor_sync(0xFFFFFFFFu, rm, 2));
            if (tg == 0)
                atomicMax(&g_rowmax[b * S + i0 + wr + 16 * mi + g + 8 * p], ordf(rm));
        }

    // col maxes
#pragma unroll
    for (int nj = 0; nj < 8; nj++)
#pragma unroll
        for (int q = 0; q < 2; q++) {
            float cm = NEGF;
#pragma unroll
            for (int mi = 0; mi < 2; mi++) {
                if (rmask[mi][0]) cm = fmaxf(cm, acc[mi][nj][q]);
                if (rmask[mi][1]) cm = fmaxf(cm, acc[mi][nj][2 + q]);
            }
            cm = fmaxf(cm, __shfl_xor_sync(0xFFFFFFFFu, cm, 4));
            cm = fmaxf(cm, __shfl_xor_sync(0xFFFFFFFFu, cm, 8));
            cm = fmaxf(cm, __shfl_xor_sync(0xFFFFFFFFu, cm, 16));
            if (g == 0)
                atomicMax(&g_colmax[b * S + j0 + wc + 8 * nj + 2 * tg + q], ordf(cm));
        }
}

// ---------------- final masked sums ----------------
__global__ void k_final(const int* __restrict__ mask1, const int* __restrict__ mask2,
                        float* __restrict__ out) {
    __shared__ float ssum[256];
    __shared__ int   scnt[256];
    const int b = blockIdx.x;
    const int tid = threadIdx.x;

    float s = 0.f;
    int   n = 0;
    for (int i = tid; i < S; i += 256) {
        int m1 = mask1[b * S + i];
        if (m1) s += deord(g_rowmax[b * S + i]);
        n += m1;
        int m2 = mask2[b * S + i];
        if (m2) s += deord(g_colmax[b * S + i]);
        n += m2;
    }
    ssum[tid] = s; scnt[tid] = n;
    __syncthreads();
    for (int o = 128; o > 0; o >>= 1) {
        if (tid < o) { ssum[tid] += ssum[tid + o]; scnt[tid] += scnt[tid + o]; }
        __syncthreads();
    }
    if (tid == 0) out[b] = ssum[0] / (float)scnt[0];
}

// ---------------- launch ----------------
extern "C" void kernel_launch(void* const* d_in, const int* in_sizes, int n_in,
                              void* d_out, int out_size) {
    const float* emb1  = (const float*)d_in[0];
    const float* emb2  = (const float*)d_in[1];
    const int*   mask1 = (const int*)d_in[2];
    const int*   mask2 = (const int*)d_in[3];
    float*       out   = (float*)d_out;

    static bool attr_set = false;
    if (!attr_set) {
        cudaFuncSetAttribute(k_gemm, cudaFuncAttributeMaxDynamicSharedMemorySize, 2 * STAGE_BYTES);
        attr_set = true;
    }

    // 1) prep (one warp per row, mask-skipped)
    k_prep<0><<<(B * S) / 8, 256>>>(emb1, mask1);
    k_prep<1><<<(B * S) / 8, 256>>>(emb2, mask2);

    // 2) GEMM + masked maxes: grid (jb=4, ib=4, b=64) = 1024 CTAs (many exit early)
    dim3 grid(S / 128, S / 128, B);
    k_gemm<<<grid, 256, 2 * STAGE_BYTES>>>(mask1, mask2);

    // 3) final
    k_final<<<B, 256>>>(mask1, mask2, out);
}

// round 16
// speedup vs baseline: 4.2466x; 1.2774x over previous
#include <cuda_runtime.h>
#include <cuda_fp16.h>
#include <cstdint>

// Problem shape (fixed by the dataset)
#define B 64
#define S 512
#define DD 512

#define NEG_ORD ((int)0xB19194D7)   // ordf(-1e9f)
#define NEGF (-1e9f)

// ---------------- global scratch (no allocations allowed) ----------------
__device__ __align__(16) __half g_A[(size_t)B * S * DD];   // normalized e1, fp16
__device__ __align__(16) __half g_B[(size_t)B * S * DD];   // normalized e2, fp16
__device__ int g_rowmax[B * S];
__device__ int g_colmax[B * S];

// ---------------- helpers ----------------
__device__ __forceinline__ int ordf(float f) {
    int i = __float_as_int(f);
    return (i >= 0) ? i : (i ^ 0x7FFFFFFF);
}
__device__ __forceinline__ float deord(int s) {
    return __int_as_float((s >= 0) ? s : (s ^ 0x7FFFFFFF));
}
__device__ __forceinline__ uint32_t smem_u32(const void* p) {
    uint32_t a;
    asm("{ .reg .u64 t; cvta.to.shared.u64 t, %1; cvt.u32.u64 %0, t; }" : "=r"(a) : "l"(p));
    return a;
}

#define CP_ASYNC16(dst, src) \
    asm volatile("cp.async.cg.shared.global [%0], [%1], 16;" :: "r"(dst), "l"(src) : "memory")
#define CP_COMMIT()  asm volatile("cp.async.commit_group;" ::: "memory")
#define CP_WAIT(n)   asm volatile("cp.async.wait_group %0;" :: "n"(n) : "memory")

#define LDSM_X4(r0, r1, r2, r3, addr) \
    asm volatile("ldmatrix.sync.aligned.m8n8.x4.shared.b16 {%0,%1,%2,%3}, [%4];" \
                 : "=r"(r0), "=r"(r1), "=r"(r2), "=r"(r3) : "r"(addr))

#define MMA_F16(c, a, b0v, b1v) \
    asm volatile("mma.sync.aligned.m16n8k16.row.col.f32.f16.f16.f32 " \
                 "{%0,%1,%2,%3}, {%4,%5,%6,%7}, {%8,%9}, {%0,%1,%2,%3};" \
                 : "+f"((c)[0]), "+f"((c)[1]), "+f"((c)[2]), "+f"((c)[3]) \
                 : "r"((a)[0]), "r"((a)[1]), "r"((a)[2]), "r"((a)[3]), "r"(b0v), "r"(b1v))

// ---------------- prep: normalize -> fp16, both sides in ONE launch ----------------
// One warp per row; blockIdx.y selects the side. Rows beyond the valid prefix
// are skipped entirely (stale/zero scratch only feeds mask-discarded outputs).
__global__ void k_prep(const float* __restrict__ e1, const float* __restrict__ e2,
                       const int* __restrict__ mask1, const int* __restrict__ mask2) {
    const int side = blockIdx.y;
    int row  = (blockIdx.x * blockDim.x + threadIdx.x) >> 5;
    int lane = threadIdx.x & 31;
    if (row >= B * S) return;

    const float* in   = side ? e2 : e1;
    const int*   mask = side ? mask2 : mask1;

    if (lane == 0) {
        if (side == 0) g_rowmax[row] = NEG_ORD; else g_colmax[row] = NEG_ORD;
    }
    if (mask[row] == 0) return;   // invalid row: never contributes

    const float4* rp = (const float4*)(in + (size_t)row * DD);

    float4 v0a = rp[2 * lane],        v0b = rp[2 * lane + 1];
    float4 v1a = rp[2 * (lane + 32)], v1b = rp[2 * (lane + 32) + 1];

    float ss = 0.f;
    ss = fmaf(v0a.x, v0a.x, ss); ss = fmaf(v0a.y, v0a.y, ss);
    ss = fmaf(v0a.z, v0a.z, ss); ss = fmaf(v0a.w, v0a.w, ss);
    ss = fmaf(v0b.x, v0b.x, ss); ss = fmaf(v0b.y, v0b.y, ss);
    ss = fmaf(v0b.z, v0b.z, ss); ss = fmaf(v0b.w, v0b.w, ss);
    ss = fmaf(v1a.x, v1a.x, ss); ss = fmaf(v1a.y, v1a.y, ss);
    ss = fmaf(v1a.z, v1a.z, ss); ss = fmaf(v1a.w, v1a.w, ss);
    ss = fmaf(v1b.x, v1b.x, ss); ss = fmaf(v1b.y, v1b.y, ss);
    ss = fmaf(v1b.z, v1b.z, ss); ss = fmaf(v1b.w, v1b.w, ss);
#pragma unroll
    for (int o = 16; o > 0; o >>= 1) ss += __shfl_xor_sync(0xFFFFFFFFu, ss, o);
    float inv = 1.0f / fmaxf(sqrtf(ss), 1e-8f);

    __half* dst = side ? g_B : g_A;

#pragma unroll
    for (int half_ = 0; half_ < 2; half_++) {
        float x[8];
        if (half_ == 0) {
            x[0] = v0a.x; x[1] = v0a.y; x[2] = v0a.z; x[3] = v0a.w;
            x[4] = v0b.x; x[5] = v0b.y; x[6] = v0b.z; x[7] = v0b.w;
        } else {
            x[0] = v1a.x; x[1] = v1a.y; x[2] = v1a.z; x[3] = v1a.w;
            x[4] = v1b.x; x[5] = v1b.y; x[6] = v1b.z; x[7] = v1b.w;
        }
        __half h[8];
#pragma unroll
        for (int u = 0; u < 8; u++) h[u] = __float2half(x[u] * inv);
        size_t idx = (size_t)row * DD + (size_t)(lane + 32 * half_) * 8;
        *(uint4*)(dst + idx) = *(uint4*)h;
    }
}

// ---------------- GEMM: fp16 mma.sync + masked row/col max ----------------
// CTA 256 threads / 8 warps, tile 128x128, k-chunk 64, 2-stage cp.async
// pipeline, XOR swizzle, warp grid 4(row)x2(col), warp tile 32x64.
// 2 CTAs/SM (fp16 single-term fits the 128-reg cap). Prefix-mask tile skip.
#define KCH 64
#define NCHUNK (DD / KCH)
#define STAGE_BYTES 32768
#define OFF_A 0
#define OFF_B 16384

__global__ __launch_bounds__(256, 2) void k_gemm(const int* __restrict__ mask1,
                                                 const int* __restrict__ mask2) {
    extern __shared__ __align__(1024) char smem[];
    __shared__ int m1s[128], m2s[128];

    const uint32_t sb = smem_u32(smem);
    const int tid  = threadIdx.x;
    const int wid  = tid >> 5;
    const int lane = tid & 31;
    const int b  = blockIdx.z;
    const int ib = blockIdx.y;
    const int jb = blockIdx.x;
    const int i0 = ib * 128;
    const int j0 = jb * 128;

    // prefix-mask tile skip: uniform across CTA, no sync executed before this
    if (mask1[b * S + i0] == 0 || mask2[b * S + j0] == 0) return;

    if (tid < 128) m1s[tid] = mask1[b * S + i0 + tid];
    else           m2s[tid - 128] = mask2[b * S + j0 + (tid - 128)];

    const __half* pA = g_A + ((size_t)b * S + i0) * DD;
    const __half* pB = g_B + ((size_t)b * S + j0) * DD;

    // loader mapping: granule G = tid + 256*u (u<4): row = G>>3, kg = G&7
    int lrow[4], lkg[4];
    uint32_t ldst[4];
#pragma unroll
    for (int u = 0; u < 4; u++) {
        int G = tid + 256 * u;
        lrow[u] = G >> 3;
        lkg[u]  = G & 7;
        ldst[u] = (uint32_t)(lrow[u] * 128 + ((lkg[u] ^ (lrow[u] & 7)) * 16));
    }

    auto issue_chunk = [&](int kc, int st) {
        uint32_t stg = sb + st * STAGE_BYTES;
        size_t kbase = (size_t)kc * KCH;
#pragma unroll
        for (int u = 0; u < 4; u++) {
            size_t so = (size_t)lrow[u] * DD + kbase + lkg[u] * 8;
            CP_ASYNC16(stg + OFF_A + ldst[u], pA + so);
            CP_ASYNC16(stg + OFF_B + ldst[u], pB + so);
        }
    };

    float acc[2][8][4];
#pragma unroll
    for (int mi = 0; mi < 2; mi++)
#pragma unroll
        for (int nj = 0; nj < 8; nj++)
#pragma unroll
            for (int r = 0; r < 4; r++) acc[mi][nj][r] = 0.f;

    const int wr = (wid & 3) * 32;
    const int wc = (wid >> 2) * 64;

    // ldmatrix lane address components
    const int a_r = (lane & 7) + 8 * ((lane >> 3) & 1);
    const int a_k = lane >> 4;
    const int b_r = (lane & 7) + 8 * (lane >> 4);
    const int b_k = (lane >> 3) & 1;

    issue_chunk(0, 0);
    CP_COMMIT();

#pragma unroll 1
    for (int t = 0; t < NCHUNK; t++) {
        if (t < NCHUNK - 1) {
            issue_chunk(t + 1, (t + 1) & 1);
            CP_COMMIT();
            CP_WAIT(1);
        } else {
            CP_WAIT(0);
        }
        __syncthreads();

        uint32_t stg = sb + (t & 1) * STAGE_BYTES;
#pragma unroll
        for (int ks = 0; ks < 4; ks++) {
            const int kg0 = ks * 2;
            uint32_t ah[2][4], bh[4][4];
#pragma unroll
            for (int mi = 0; mi < 2; mi++) {
                int row = wr + 16 * mi + a_r;
                uint32_t ad = stg + (uint32_t)(row * 128 + (((kg0 + a_k) ^ (row & 7)) * 16));
                LDSM_X4(ah[mi][0], ah[mi][1], ah[mi][2], ah[mi][3], ad + OFF_A);
            }
#pragma unroll
            for (int nb = 0; nb < 4; nb++) {
                int row = wc + 16 * nb + b_r;
                uint32_t bd = stg + (uint32_t)(row * 128 + (((kg0 + b_k) ^ (row & 7)) * 16));
                LDSM_X4(bh[nb][0], bh[nb][1], bh[nb][2], bh[nb][3], bd + OFF_B);
            }
#pragma unroll
            for (int mi = 0; mi < 2; mi++)
#pragma unroll
                for (int nb = 0; nb < 4; nb++) {
                    MMA_F16(acc[mi][2 * nb],     ah[mi], bh[nb][0], bh[nb][1]);
                    MMA_F16(acc[mi][2 * nb + 1], ah[mi], bh[nb][2], bh[nb][3]);
                }
        }
        __syncthreads();
    }

    // -------- epilogue: masked row/col maxes from D fragments --------
    const int g  = lane >> 2;
    const int tg = lane & 3;

    int cmask[8][2];
#pragma unroll
    for (int nj = 0; nj < 8; nj++) {
        cmask[nj][0] = m2s[wc + 8 * nj + 2 * tg];
        cmask[nj][1] = m2s[wc + 8 * nj + 2 * tg + 1];
    }
    int rmask[2][2];
#pragma unroll
    for (int mi = 0; mi < 2; mi++) {
        rmask[mi][0] = m1s[wr + 16 * mi + g];
        rmask[mi][1] = m1s[wr + 16 * mi + g + 8];
    }

    // row maxes
#pragma unroll
    for (int mi = 0; mi < 2; mi++)
#pragma unroll
        for (int p = 0; p < 2; p++) {
            float rm = NEGF;
#pragma unroll
            for (int nj = 0; nj < 8; nj++) {
                if (cmask[nj][0]) rm = fmaxf(rm, acc[mi][nj][2 * p]);
                if (cmask[nj][1]) rm = fmaxf(rm, acc[mi][nj][2 * p + 1]);
            }
            rm = fmaxf(rm, __shfl_xor_sync(0xFFFFFFFFu, rm, 1));
            rm = fmaxf(rm, __shfl_xor_sync(0xFFFFFFFFu, rm, 2));
            if (tg == 0)
                atomicMax(&g_rowmax[b * S + i0 + wr + 16 * mi + g + 8 * p], ordf(rm));
        }

    // col maxes
#pragma unroll
    for (int nj = 0; nj < 8; nj++)
#pragma unroll
        for (int q = 0; q < 2; q++) {
            float cm = NEGF;
#pragma unroll
            for (int mi = 0; mi < 2; mi++) {
                if (rmask[mi][0]) cm = fmaxf(cm, acc[mi][nj][q]);
                if (rmask[mi][1]) cm = fmaxf(cm, acc[mi][nj][2 + q]);
            }
            cm = fmaxf(cm, __shfl_xor_sync(0xFFFFFFFFu, cm, 4));
            cm = fmaxf(cm, __shfl_xor_sync(0xFFFFFFFFu, cm, 8));
            cm = fmaxf(cm, __shfl_xor_sync(0xFFFFFFFFu, cm, 16));
            if (g == 0)
                atomicMax(&g_colmax[b * S + j0 + wc + 8 * nj + 2 * tg + q], ordf(cm));
        }
}

// ---------------- final masked sums ----------------
__global__ void k_final(const int* __restrict__ mask1, const int* __restrict__ mask2,
                        float* __restrict__ out) {
    __shared__ float ssum[256];
    __shared__ int   scnt[256];
    const int b = blockIdx.x;
    const int tid = threadIdx.x;

    float s = 0.f;
    int   n = 0;
    for (int i = tid; i < S; i += 256) {
        int m1 = mask1[b * S + i];
        if (m1) s += deord(g_rowmax[b * S + i]);
        n += m1;
        int m2 = mask2[b * S + i];
        if (m2) s += deord(g_colmax[b * S + i]);
        n += m2;
    }
    ssum[tid] = s; scnt[tid] = n;
    __syncthreads();
    for (int o = 128; o > 0; o >>= 1) {
        if (tid < o) { ssum[tid] += ssum[tid + o]; scnt[tid] += scnt[tid + o]; }
        __syncthreads();
    }
    if (tid == 0) out[b] = ssum[0] / (float)scnt[0];
}

// ---------------- launch ----------------
extern "C" void kernel_launch(void* const* d_in, const int* in_sizes, int n_in,
                              void* d_out, int out_size) {
    const float* emb1  = (const float*)d_in[0];
    const float* emb2  = (const float*)d_in[1];
    const int*   mask1 = (const int*)d_in[2];
    const int*   mask2 = (const int*)d_in[3];
    float*       out   = (float*)d_out;

    static bool attr_set = false;
    if (!attr_set) {
        cudaFuncSetAttribute(k_gemm, cudaFuncAttributeMaxDynamicSharedMemorySize, 2 * STAGE_BYTES);
        attr_set = true;
    }

    // 1) prep: both sides in one launch (grid.y = side)
    dim3 pgrid((B * S) / 8, 2);
    k_prep<<<pgrid, 256>>>(emb1, emb2, mask1, mask2);

    // 2) GEMM + masked maxes: grid (jb=4, ib=4, b=64) = 1024 CTAs (many exit
    //    early), 2 CTAs/SM
    dim3 grid(S / 128, S / 128, B);
    k_gemm<<<grid, 256, 2 * STAGE_BYTES>>>(mask1, mask2);

    // 3) final
    k_final<<<B, 256>>>(mask1, mask2, out);
}